// round 8
// baseline (speedup 1.0000x reference)
#include <cuda_runtime.h>
#include <cstdint>

// Problem constants
#define BATCH 16
#define CH    16
#define FIL   32
#define IMH   256
#define IMW   256

// Tiling: 8 x 32 output tile per CTA
#define TH 8
#define TW 32
#define HALO_H 10        // TH + 2
#define HALO_W 34        // TW + 2
#define SROW   36        // float row stride: mult of 4 -> 16B-aligned rows, conflict-free
#define NTHREADS 256

typedef unsigned long long u64;

#define SMEM_IN_FLOATS (CH * HALO_H * SROW)        // 5760 floats = 23040 B
#define SMEM_W_U64     (CH * 9 * FIL)              // 4608 u64 dup weights = 36864 B
#define SMEM_BYTES     (SMEM_IN_FLOATS * 4 + SMEM_W_U64 * 8)   // 59904 B -> 3 CTAs/SM

__device__ __forceinline__ u64 pack2(float lo, float hi) {
    u64 r;
    asm("mov.b64 %0, {%1, %2};" : "=l"(r) : "f"(lo), "f"(hi));
    return r;
}
__device__ __forceinline__ void unpack2(u64 v, float& lo, float& hi) {
    asm("mov.b64 {%0, %1}, %2;" : "=f"(lo), "=f"(hi) : "l"(v));
}
// packed dual fp32 FMA (sm_103a)
__device__ __forceinline__ u64 ffma2(u64 a, u64 b, u64 c) {
    u64 d;
    asm("fma.rn.f32x2 %0, %1, %2, %3;" : "=l"(d) : "l"(a), "l"(b), "l"(c));
    return d;
}

extern __shared__ float smem[];

__global__ __launch_bounds__(NTHREADS, 3)
void conv3x3_sigmoid_v3(const float* __restrict__ x,
                        const float* __restrict__ wgt,
                        const float* __restrict__ bias,
                        float* __restrict__ out) {
    float* s_in = smem;                                  // [CH][HALO_H][SROW], natural floats
    u64*   s_w  = (u64*)(smem + SMEM_IN_FLOATS);         // [CH][3][3][FIL], each {w,w}

    const int tid = threadIdx.x;
    const int b   = blockIdx.z;
    const int h0  = blockIdx.y * TH;
    const int w0  = blockIdx.x * TW;

    // ---- Weights: duplicate each scalar into a f32x2 pair ----
    // gmem layout: (c*9 + kh*3 + kw)*32 + f  -> same index order in s_w
    #pragma unroll
    for (int i = tid; i < CH * 9 * FIL; i += NTHREADS) {
        float w = wgt[i];
        s_w[i] = pack2(w, w);
    }

    // ---- Input halo tile, natural floats (zero-padded borders) ----
    const int total_in = CH * HALO_H * HALO_W;    // 5440
    for (int i = tid; i < total_in; i += NTHREADS) {
        int c   = i / (HALO_H * HALO_W);
        int rem = i - c * (HALO_H * HALO_W);
        int row = rem / HALO_W;
        int col = rem - row * HALO_W;
        int gh = h0 - 1 + row;
        int gw = w0 - 1 + col;
        float v = 0.0f;
        if (gh >= 0 && gh < IMH && gw >= 0 && gw < IMW)
            v = x[((b * CH + c) * IMH + gh) * IMW + gw];
        s_in[(c * HALO_H + row) * SROW + col] = v;
    }
    __syncthreads();

    // ---- Thread mapping ----
    // fg = tid>>5 (warp id): uniform within warp -> weight loads broadcast.
    // lanes: r = l&7 spans 8 rows -> 4r banks mod 32 distinct -> conflict-free LDS.128.
    const int fg = tid >> 5;         // filter group: 4 filters, 0..7
    const int pg = tid & 31;
    const int r  = pg & 7;           // output row in tile
    const int ws = pg >> 3;          // 8-wide pixel segment, 0..3

    // acc[t][j]: pixel pair t (pixels 2t,2t+1), filter j of this thread's 4
    u64 acc[4][4];
    #pragma unroll
    for (int t = 0; t < 4; ++t)
        #pragma unroll
        for (int j = 0; j < 4; ++j) acc[t][j] = 0ull;

    #pragma unroll 1
    for (int c = 0; c < CH; ++c) {
        #pragma unroll
        for (int kh = 0; kh < 3; ++kh) {
            // x row: 10 floats -> even pairs e[0..4] straight from smem
            const u64* rp = (const u64*)(s_in + (c * HALO_H + r + kh) * SROW + ws * 8);
            u64 e[5];
            {
                ulonglong2 v01 = ((const ulonglong2*)rp)[0];   // LDS.128
                ulonglong2 v23 = ((const ulonglong2*)rp)[1];   // LDS.128
                e[0] = v01.x; e[1] = v01.y;
                e[2] = v23.x; e[3] = v23.y;
                e[4] = rp[4];                                   // LDS.64
            }
            // odd-shift pairs o[t] = {x[2t+1], x[2t+2]}
            u64 o[4];
            #pragma unroll
            for (int t = 0; t < 4; ++t) {
                float lo_junk, hiA, loB, hi_junk;
                unpack2(e[t],     lo_junk, hiA);
                unpack2(e[t + 1], loB,     hi_junk);
                o[t] = pack2(hiA, loB);
            }

            const u64* wk = s_w + (c * 9 + kh * 3) * FIL + fg * 4;
            #pragma unroll
            for (int kw = 0; kw < 3; ++kw) {
                // 4 dup weight pairs for this kw: 2x LDS.128 broadcast
                ulonglong2 w01 = ((const ulonglong2*)(wk + kw * FIL))[0];
                ulonglong2 w23 = ((const ulonglong2*)(wk + kw * FIL))[1];
                u64 w[4] = {w01.x, w01.y, w23.x, w23.y};
                #pragma unroll
                for (int t = 0; t < 4; ++t) {
                    u64 xp = (kw == 0) ? e[t] : (kw == 1) ? o[t] : e[t + 1];
                    #pragma unroll
                    for (int j = 0; j < 4; ++j)
                        acc[t][j] = ffma2(xp, w[j], acc[t][j]);
                }
            }
        }
    }

    // ---- Epilogue: +bias, sigmoid, store ----
    const int h  = h0 + r;
    const int wc = w0 + ws * 8;      // multiple of 8 -> 16B aligned
    #pragma unroll
    for (int j = 0; j < 4; ++j) {
        const int f = fg * 4 + j;
        float v[8];
        #pragma unroll
        for (int t = 0; t < 4; ++t) unpack2(acc[t][j], v[2 * t], v[2 * t + 1]);

        const float* bp = bias + (f * IMH + h) * IMW + wc;
        float4 bb0 = *(const float4*)(bp);
        float4 bb1 = *(const float4*)(bp + 4);
        v[0] += bb0.x; v[1] += bb0.y; v[2] += bb0.z; v[3] += bb0.w;
        v[4] += bb1.x; v[5] += bb1.y; v[6] += bb1.z; v[7] += bb1.w;

        #pragma unroll
        for (int i = 0; i < 8; ++i)
            v[i] = 1.0f / (1.0f + __expf(-v[i]));

        float* op = out + (((size_t)b * FIL + f) * IMH + h) * IMW + wc;
        *(float4*)(op)     = make_float4(v[0], v[1], v[2], v[3]);
        *(float4*)(op + 4) = make_float4(v[4], v[5], v[6], v[7]);
    }
}

extern "C" void kernel_launch(void* const* d_in, const int* in_sizes, int n_in,
                              void* d_out, int out_size) {
    const float* x    = (const float*)d_in[0];
    const float* wgt  = (const float*)d_in[1];
    const float* bias = (const float*)d_in[2];
    float* out = (float*)d_out;

    cudaFuncSetAttribute(conv3x3_sigmoid_v3,
                         cudaFuncAttributeMaxDynamicSharedMemorySize, SMEM_BYTES);

    dim3 grid(IMW / TW, IMH / TH, BATCH);   // (8, 32, 16) = 4096 CTAs
    conv3x3_sigmoid_v3<<<grid, NTHREADS, SMEM_BYTES>>>(x, wgt, bias, out);
}

// round 9
// speedup vs baseline: 1.0013x; 1.0013x over previous
#include <cuda_runtime.h>
#include <cstdint>

// Problem constants
#define BATCH 16
#define CH    16
#define FIL   32
#define IMH   256
#define IMW   256

// Tiling: 8 x 32 output tile per CTA
#define TH 8
#define TW 32
#define HALO_H 10        // TH + 2
#define HALO_W 34        // TW + 2
#define SROW   36        // float row stride: mult of 4 -> 16B-aligned rows, conflict-free
#define NTHREADS 256

typedef unsigned long long u64;

#define SMEM_IN_FLOATS (CH * HALO_H * SROW)        // 5760 floats = 23040 B
#define SMEM_W_U64     (CH * 9 * FIL)              // 4608 u64 dup weights = 36864 B
#define SMEM_BYTES     (SMEM_IN_FLOATS * 4 + SMEM_W_U64 * 8)   // 59904 B -> 3 CTAs/SM

__device__ __forceinline__ u64 pack2(float lo, float hi) {
    u64 r;
    asm("mov.b64 %0, {%1, %2};" : "=l"(r) : "f"(lo), "f"(hi));
    return r;
}
__device__ __forceinline__ void unpack2(u64 v, float& lo, float& hi) {
    asm("mov.b64 {%0, %1}, %2;" : "=f"(lo), "=f"(hi) : "l"(v));
}
// packed dual fp32 FMA (sm_103a)
__device__ __forceinline__ u64 ffma2(u64 a, u64 b, u64 c) {
    u64 d;
    asm("fma.rn.f32x2 %0, %1, %2, %3;" : "=l"(d) : "l"(a), "l"(b), "l"(c));
    return d;
}

extern __shared__ float smem[];

__global__ __launch_bounds__(NTHREADS, 3)
void conv3x3_sigmoid_v3(const float* __restrict__ x,
                        const float* __restrict__ wgt,
                        const float* __restrict__ bias,
                        float* __restrict__ out) {
    float* s_in = smem;                                  // [CH][HALO_H][SROW], natural floats
    u64*   s_w  = (u64*)(smem + SMEM_IN_FLOATS);         // [CH][3][3][FIL], each {w,w}

    const int tid = threadIdx.x;
    const int b   = blockIdx.z;
    const int h0  = blockIdx.y * TH;
    const int w0  = blockIdx.x * TW;

    // ---- Weights: duplicate each scalar into a f32x2 pair ----
    // gmem layout: (c*9 + kh*3 + kw)*32 + f  -> same index order in s_w
    #pragma unroll
    for (int i = tid; i < CH * 9 * FIL; i += NTHREADS) {
        float w = wgt[i];
        s_w[i] = pack2(w, w);
    }

    // ---- Input halo tile, natural floats (zero-padded borders) ----
    const int total_in = CH * HALO_H * HALO_W;    // 5440
    for (int i = tid; i < total_in; i += NTHREADS) {
        int c   = i / (HALO_H * HALO_W);
        int rem = i - c * (HALO_H * HALO_W);
        int row = rem / HALO_W;
        int col = rem - row * HALO_W;
        int gh = h0 - 1 + row;
        int gw = w0 - 1 + col;
        float v = 0.0f;
        if (gh >= 0 && gh < IMH && gw >= 0 && gw < IMW)
            v = x[((b * CH + c) * IMH + gh) * IMW + gw];
        s_in[(c * HALO_H + row) * SROW + col] = v;
    }
    __syncthreads();

    // ---- Thread mapping ----
    // fg = tid>>5 (warp id): uniform within warp -> weight loads broadcast.
    // lanes: r = l&7 spans 8 rows -> 4r banks mod 32 distinct -> conflict-free LDS.128.
    const int fg = tid >> 5;         // filter group: 4 filters, 0..7
    const int pg = tid & 31;
    const int r  = pg & 7;           // output row in tile
    const int ws = pg >> 3;          // 8-wide pixel segment, 0..3

    // acc[t][j]: pixel pair t (pixels 2t,2t+1), filter j of this thread's 4
    u64 acc[4][4];
    #pragma unroll
    for (int t = 0; t < 4; ++t)
        #pragma unroll
        for (int j = 0; j < 4; ++j) acc[t][j] = 0ull;

    #pragma unroll 1
    for (int c = 0; c < CH; ++c) {
        #pragma unroll
        for (int kh = 0; kh < 3; ++kh) {
            // x row: 10 floats -> even pairs e[0..4] straight from smem
            const u64* rp = (const u64*)(s_in + (c * HALO_H + r + kh) * SROW + ws * 8);
            u64 e[5];
            {
                ulonglong2 v01 = ((const ulonglong2*)rp)[0];   // LDS.128
                ulonglong2 v23 = ((const ulonglong2*)rp)[1];   // LDS.128
                e[0] = v01.x; e[1] = v01.y;
                e[2] = v23.x; e[3] = v23.y;
                e[4] = rp[4];                                   // LDS.64
            }
            // odd-shift pairs o[t] = {x[2t+1], x[2t+2]}
            u64 o[4];
            #pragma unroll
            for (int t = 0; t < 4; ++t) {
                float lo_junk, hiA, loB, hi_junk;
                unpack2(e[t],     lo_junk, hiA);
                unpack2(e[t + 1], loB,     hi_junk);
                o[t] = pack2(hiA, loB);
            }

            const u64* wk = s_w + (c * 9 + kh * 3) * FIL + fg * 4;
            #pragma unroll
            for (int kw = 0; kw < 3; ++kw) {
                // 4 dup weight pairs for this kw: 2x LDS.128 broadcast
                ulonglong2 w01 = ((const ulonglong2*)(wk + kw * FIL))[0];
                ulonglong2 w23 = ((const ulonglong2*)(wk + kw * FIL))[1];
                u64 w[4] = {w01.x, w01.y, w23.x, w23.y};
                #pragma unroll
                for (int t = 0; t < 4; ++t) {
                    u64 xp = (kw == 0) ? e[t] : (kw == 1) ? o[t] : e[t + 1];
                    #pragma unroll
                    for (int j = 0; j < 4; ++j)
                        acc[t][j] = ffma2(xp, w[j], acc[t][j]);
                }
            }
        }
    }

    // ---- Epilogue: +bias, sigmoid, store ----
    const int h  = h0 + r;
    const int wc = w0 + ws * 8;      // multiple of 8 -> 16B aligned
    #pragma unroll
    for (int j = 0; j < 4; ++j) {
        const int f = fg * 4 + j;
        float v[8];
        #pragma unroll
        for (int t = 0; t < 4; ++t) unpack2(acc[t][j], v[2 * t], v[2 * t + 1]);

        const float* bp = bias + (f * IMH + h) * IMW + wc;
        float4 bb0 = *(const float4*)(bp);
        float4 bb1 = *(const float4*)(bp + 4);
        v[0] += bb0.x; v[1] += bb0.y; v[2] += bb0.z; v[3] += bb0.w;
        v[4] += bb1.x; v[5] += bb1.y; v[6] += bb1.z; v[7] += bb1.w;

        #pragma unroll
        for (int i = 0; i < 8; ++i)
            v[i] = 1.0f / (1.0f + __expf(-v[i]));

        float* op = out + (((size_t)b * FIL + f) * IMH + h) * IMW + wc;
        *(float4*)(op)     = make_float4(v[0], v[1], v[2], v[3]);
        *(float4*)(op + 4) = make_float4(v[4], v[5], v[6], v[7]);
    }
}

extern "C" void kernel_launch(void* const* d_in, const int* in_sizes, int n_in,
                              void* d_out, int out_size) {
    const float* x    = (const float*)d_in[0];
    const float* wgt  = (const float*)d_in[1];
    const float* bias = (const float*)d_in[2];
    float* out = (float*)d_out;

    cudaFuncSetAttribute(conv3x3_sigmoid_v3,
                         cudaFuncAttributeMaxDynamicSharedMemorySize, SMEM_BYTES);

    dim3 grid(IMW / TW, IMH / TH, BATCH);   // (8, 32, 16) = 4096 CTAs
    conv3x3_sigmoid_v3<<<grid, NTHREADS, SMEM_BYTES>>>(x, wgt, bias, out);
}